// round 5
// baseline (speedup 1.0000x reference)
#include <cuda_runtime.h>
#include <math.h>

#define BB 8
#define C0 16
#define C1 64
#define C2 64
#define TT 12
#define NN 256
#define KTT 3
#define HH 8
#define T1 10
#define T2 8
#define ALPHA 0.2f

// ---------------- device scratch (no allocations allowed) ----------------
__device__ float g_v1[HH * C1];
__device__ float g_v2[HH * C1];
__device__ int   g_nbr[NN * NN];
__device__ int   g_cnt[NN];
__device__ float g_lnw[C2 * NN];            // transposed [c][n]
__device__ float g_lnb[C2 * NN];
__device__ float g_xg[BB * T1 * NN * C1];   // x_t1 in (b,t,n,c)
__device__ float g_e1[BB * T1 * HH * NN];
__device__ float g_e2[BB * T1 * HH * NN];
__device__ float g_xs[BB * T1 * NN * C1];   // x_t1 + gat
__device__ float g_ys[BB * T2 * NN * C2];   // relu(conv2)+res, (bt,n,c)
__device__ float g_part[BB * T2 * 4 * 2];   // per-chunk LN partials {S,Q}

__device__ __forceinline__ float ftanh(float x) {
    x = fminf(fmaxf(x, -15.f), 15.f);
    float e = __expf(2.f * x);
    return (e - 1.f) / (e + 1.f);
}

// ---------------- K0: prep, parallelized over 16 blocks -------------------
__global__ void k0_prep(const float* __restrict__ adj,
                        const float* __restrict__ W,
                        const float* __restrict__ a,
                        const float* __restrict__ lnw,
                        const float* __restrict__ lnb) {
    int tid = threadIdx.x, lane = tid & 31, w = tid >> 5;
    int blk = blockIdx.x;

    // v vectors: block 0 only
    if (blk == 0) {
        for (int idx = tid; idx < HH * C1; idx += 256) {
            int h = idx / C1, c = idx % C1;
            const float* Wr = W + (h * C1 + c) * C1;
            const float* ar = a + h * 2 * C1;
            float s1 = 0.f, s2 = 0.f;
            for (int d = 0; d < C1; d++) {
                float wv = Wr[d];
                s1 = fmaf(wv, ar[d], s1);
                s2 = fmaf(wv, ar[C1 + d], s2);
            }
            g_v1[idx] = s1;
            g_v2[idx] = s2;
        }
    }
    // CSR via warp ballot compaction: 16 rows per block, 2 per warp
    for (int r2 = 0; r2 < 2; r2++) {
        int i = blk * 16 + w * 2 + r2;
        const float* row = adj + i * NN;
        int cnt = 0;
#pragma unroll
        for (int c = 0; c < 8; c++) {
            int j = c * 32 + lane;
            bool bset = row[j] > 0.f;
            unsigned mask = __ballot_sync(0xffffffffu, bset);
            if (bset) {
                int pos = cnt + __popc(mask & ((1u << lane) - 1));
                g_nbr[i * NN + pos] = j;
            }
            cnt += __popc(mask);
        }
        if (lane == 0) g_cnt[i] = cnt;
        int cc = cnt > 96 ? 96 : cnt;          // K2 supports up to 3 chunks
        int pc = ((cc + 31) >> 5) << 5;
        for (int k = cnt + lane; k < pc; k += 32) g_nbr[i * NN + k] = 0;
    }
    // layernorm params transposed to [c][n], strided across blocks
    for (int idx = blk * 256 + tid; idx < NN * C2; idx += 16 * 256) {
        int n = idx / C2, c = idx % C2;
        g_lnw[c * NN + n] = lnw[idx];
        g_lnb[c * NN + n] = lnb[idx];
    }
}

// ---------------- K1: conv1 + GLU gate + e-score projections -------------
// grid (B*T1, 2): each block 128 nodes; 256 threads; ~22KB smem
#define K1_SMEM ((48*128 + 48*128 + 128 + 128*67 + 2*HH*C1) * 4)
__global__ __launch_bounds__(256) void k1_conv1(const float* __restrict__ x,
                                                const float* __restrict__ w1,
                                                const float* __restrict__ b1) {
    extern __shared__ float sm[];
    float* xsm = sm;                      // [48][128]  (ci*3+kt, nl)
    float* w1s = xsm + 48 * 128;          // [48][128]  (ci*3+kt, co)
    float* b1s = w1s + 48 * 128;          // [128]
    float* xt  = b1s + 128;               // [128][67]
    float* v1s = xt + 128 * 67;           // [512]
    float* v2s = v1s + HH * C1;           // [512]

    int bt = blockIdx.x;
    int b = bt / T1, t = bt % T1;
    int n0 = blockIdx.y * 128;
    int tid = threadIdx.x;

    for (int idx = tid; idx < C0 * KTT * 128; idx += 256) {
        int r = idx >> 7, nl = idx & 127;
        int ci = r / KTT, kt = r % KTT;
        xsm[idx] = x[((b * C0 + ci) * TT + (t + kt)) * NN + n0 + nl];
    }
    for (int idx = tid; idx < 48 * 128; idx += 256) {
        int r = idx >> 7, co = idx & 127;
        int ci = r / KTT, kt = r % KTT;
        w1s[idx] = w1[(co * C0 + ci) * KTT + kt];
    }
    if (tid < 128) b1s[tid] = b1[tid];
    for (int idx = tid; idx < HH * C1; idx += 256) {
        v1s[idx] = g_v1[idx];
        v2s[idx] = g_v2[idx];
    }
    __syncthreads();

    int co = tid & 63, g = tid >> 6;
    for (int nl = g; nl < 64; nl += 4) {
        int nl2 = nl + 64;
        float a0 = b1s[co], a1 = b1s[co + 64];
        float c0 = a0, c1 = a1;
#pragma unroll
        for (int r = 0; r < 48; r++) {
            float xva = xsm[r * 128 + nl];
            float xvb = xsm[r * 128 + nl2];
            float w0  = w1s[r * 128 + co];
            float wg  = w1s[r * 128 + co + 64];
            a0 = fmaf(xva, w0, a0);
            a1 = fmaf(xva, wg, a1);
            c0 = fmaf(xvb, w0, c0);
            c1 = fmaf(xvb, wg, c1);
        }
        float xin_a = (co < C0) ? xsm[(co * KTT + 2) * 128 + nl]  : 0.f;
        float xin_b = (co < C0) ? xsm[(co * KTT + 2) * 128 + nl2] : 0.f;
        float va = (a0 + xin_a) / (1.f + __expf(-a1));
        float vb = (c0 + xin_b) / (1.f + __expf(-c1));
        xt[nl  * 67 + co] = va;
        xt[nl2 * 67 + co] = vb;
        g_xg[(bt * NN + n0 + nl ) * C1 + co] = va;
        g_xg[(bt * NN + n0 + nl2) * C1 + co] = vb;
    }
    __syncthreads();

    // e-score: node nl = tid&127, head group (tid>>7)*4, 8 accumulators
    {
        int nl = tid & 127;
        int hb = (tid >> 7) * 4;
        const float* row = &xt[nl * 67];
        float s1[4], s2[4];
#pragma unroll
        for (int hh = 0; hh < 4; hh++) { s1[hh] = 0.f; s2[hh] = 0.f; }
#pragma unroll 4
        for (int c = 0; c < C1; c++) {
            float v = row[c];
#pragma unroll
            for (int hh = 0; hh < 4; hh++) {
                s1[hh] = fmaf(v, v1s[(hb + hh) * C1 + c], s1[hh]);
                s2[hh] = fmaf(v, v2s[(hb + hh) * C1 + c], s2[hh]);
            }
        }
#pragma unroll
        for (int hh = 0; hh < 4; hh++) {
            g_e1[(bt * HH + hb + hh) * NN + n0 + nl] = s1[hh];
            g_e2[(bt * HH + hb + hh) * NN + n0 + nl] = s2[hh];
        }
    }
}

// ---------------- K2: sparse GAT, all heads fused in matvec ---------------
// grid (B*T1, 4), 256 threads (8 warps), 8 rows/warp
// smem: xt [256][66], e2s [8][256], per-warp pbuf [96][12] ({p0..p7,j})
#define K2_SMEM ((NN*66 + HH*NN + 8*96*12) * 4)
__global__ __launch_bounds__(256, 2) void k2_gat() {
    extern __shared__ float sm[];
    float* xt  = sm;                   // [256][66]
    float* e2s = xt + NN * 66;         // [8][256]
    float* pb  = e2s + HH * NN;        // 8 x [96][12]

    int bt = blockIdx.x;
    int tid = threadIdx.x, lane = tid & 31, w = tid >> 5;

    for (int idx = tid; idx < NN * C1; idx += 256) {
        xt[(idx >> 6) * 66 + (idx & 63)] = g_xg[bt * NN * C1 + idx];
    }
    for (int idx = tid; idx < HH * NN; idx += 256) {
        e2s[idx] = g_e2[bt * HH * NN + idx];
    }
    __syncthreads();

    float* pbw = pb + w * (96 * 12);
    int cb = 2 * lane;

    for (int rr = 0; rr < 8; rr++) {
        int i = blockIdx.y * 64 + (w << 3) + rr;
        int cnt = g_cnt[i];
        if (cnt > 96) cnt = 96;
        int nch = (cnt + 31) >> 5;
        const int* nb = g_nbr + i * NN;

        int jreg[3];
#pragma unroll
        for (int q = 0; q < 3; q++)
            jreg[q] = (q < nch) ? nb[(q << 5) + lane] : 0;
#pragma unroll
        for (int q = 0; q < 3; q++)
            if (q < nch) pbw[((q << 5) + lane) * 12 + 8] = __int_as_float(jreg[q]);

        float inv[HH];
#pragma unroll
        for (int h = 0; h < HH; h++) {
            float e1i = g_e1[(bt * HH + h) * NN + i];
            float s[3];
            float m = -3.4e38f;
#pragma unroll
            for (int q = 0; q < 3; q++) {
                if (q < nch) {
                    int k = (q << 5) + lane;
                    float sc = e1i + e2s[h * NN + jreg[q]];
                    sc = sc > 0.f ? sc : ALPHA * sc;
                    sc = (k < cnt) ? sc : -3.4e38f;
                    s[q] = sc;
                    m = fmaxf(m, sc);
                }
            }
#pragma unroll
            for (int o = 16; o; o >>= 1)
                m = fmaxf(m, __shfl_xor_sync(0xffffffffu, m, o));
            float ss = 0.f;
#pragma unroll
            for (int q = 0; q < 3; q++) {
                if (q < nch) {
                    float e = __expf(s[q] - m);   // padded -> 0 exactly
                    ss += e;
                    pbw[((q << 5) + lane) * 12 + h] = e;
                }
            }
#pragma unroll
            for (int o = 16; o; o >>= 1)
                ss += __shfl_xor_sync(0xffffffffu, ss, o);
            inv[h] = 1.f / ss;
        }
        __syncwarp();

        float a0[HH], a1[HH];
#pragma unroll
        for (int h = 0; h < HH; h++) { a0[h] = 0.f; a1[h] = 0.f; }

        int pcnt = nch << 5;
#pragma unroll 4
        for (int k = 0; k < pcnt; k++) {
            const float* row = pbw + k * 12;
            float4 pA = *(const float4*)(row);
            float4 pB = *(const float4*)(row + 4);
            int j = __float_as_int(row[8]);
            float2 xv = *(const float2*)(xt + j * 66 + cb);
            a0[0] = fmaf(pA.x, xv.x, a0[0]); a1[0] = fmaf(pA.x, xv.y, a1[0]);
            a0[1] = fmaf(pA.y, xv.x, a0[1]); a1[1] = fmaf(pA.y, xv.y, a1[1]);
            a0[2] = fmaf(pA.z, xv.x, a0[2]); a1[2] = fmaf(pA.z, xv.y, a1[2]);
            a0[3] = fmaf(pA.w, xv.x, a0[3]); a1[3] = fmaf(pA.w, xv.y, a1[3]);
            a0[4] = fmaf(pB.x, xv.x, a0[4]); a1[4] = fmaf(pB.x, xv.y, a1[4]);
            a0[5] = fmaf(pB.y, xv.x, a0[5]); a1[5] = fmaf(pB.y, xv.y, a1[5]);
            a0[6] = fmaf(pB.z, xv.x, a0[6]); a1[6] = fmaf(pB.z, xv.y, a1[6]);
            a0[7] = fmaf(pB.w, xv.x, a0[7]); a1[7] = fmaf(pB.w, xv.y, a1[7]);
        }
        __syncwarp();

        float g0 = 0.f, g1 = 0.f;
#pragma unroll
        for (int h = 0; h < HH; h++) {
            g0 += ftanh(a0[h] * inv[h]);
            g1 += ftanh(a1[h] * inv[h]);
        }
        float2 base = *(const float2*)(xt + i * 66 + cb);
        float2 outv;
        outv.x = base.x + g0 * 0.125f;
        outv.y = base.y + g1 * 0.125f;
        *(float2*)(g_xs + (bt * NN + i) * C1 + cb) = outv;
    }
}

// ---------------- K3a: conv2 + residual + relu + LN partials -------------
// grid (B*T2, 4): each block 64 nodes; 256 threads
#define K3A_SMEM ((192*64 + 64 + 3*64*64 + 16) * 4)
__global__ __launch_bounds__(256, 2) void k3a_conv2(const float* __restrict__ w2,
                                                    const float* __restrict__ b2) {
    extern __shared__ float sm[];
    float* w2s = sm;                    // [192][64]
    float* b2s = w2s + 192 * 64;        // [64]
    float* xs3 = b2s + 64;              // [3][64][64]
    float* red = xs3 + 3 * 64 * 64;     // [16]

    int bt = blockIdx.x;
    int b = bt / T2, t = bt % T2;
    int n0 = blockIdx.y * 64;
    int tid = threadIdx.x, lane = tid & 31, w = tid >> 5;

    for (int idx = tid; idx < 192 * 64; idx += 256) {
        int r = idx >> 6, co = idx & 63;
        int ci = r / KTT, kt = r % KTT;
        w2s[idx] = w2[(co * C1 + ci) * KTT + kt];
    }
    if (tid < 64) b2s[tid] = b2[tid];
    for (int idx = tid; idx < 3 * 64 * 64; idx += 256) {
        int kt = idx / 4096, rem = idx & 4095;
        int nl = rem >> 6, ci = rem & 63;
        xs3[idx] = g_xs[((b * T1 + t + kt) * NN + n0 + nl) * C1 + ci];
    }
    __syncthreads();

    int co = tid & 63, g = tid >> 6;
    float lsum = 0.f, lsq = 0.f;

    for (int nl = g; nl < 32; nl += 4) {
        int nl2 = nl + 32;
        float a = b2s[co], c = a;
#pragma unroll
        for (int kt = 0; kt < KTT; kt++) {
#pragma unroll
            for (int ci = 0; ci < C1; ci++) {
                float wv = w2s[(ci * KTT + kt) * 64 + co];
                a = fmaf(xs3[(kt * 64 + nl ) * 64 + ci], wv, a);
                c = fmaf(xs3[(kt * 64 + nl2) * 64 + ci], wv, c);
            }
        }
        float ra = a + xs3[(2 * 64 + nl ) * 64 + co];
        float rc = c + xs3[(2 * 64 + nl2) * 64 + co];
        ra = ra > 0.f ? ra : 0.f;
        rc = rc > 0.f ? rc : 0.f;
        g_ys[(bt * NN + n0 + nl ) * C2 + co] = ra;
        g_ys[(bt * NN + n0 + nl2) * C2 + co] = rc;
        lsum += ra + rc;
        lsq  += ra * ra + rc * rc;
    }

#pragma unroll
    for (int o = 16; o; o >>= 1) {
        lsum += __shfl_xor_sync(0xffffffffu, lsum, o);
        lsq  += __shfl_xor_sync(0xffffffffu, lsq,  o);
    }
    if (lane == 0) { red[w] = lsum; red[8 + w] = lsq; }
    __syncthreads();
    if (tid == 0) {
        float S = 0.f, Q = 0.f;
#pragma unroll
        for (int k = 0; k < 8; k++) { S += red[k]; Q += red[8 + k]; }
        g_part[(bt * 4 + blockIdx.y) * 2 + 0] = S;
        g_part[(bt * 4 + blockIdx.y) * 2 + 1] = Q;
    }
}

// ---------------- K3b: LN finalize + transpose write ----------------------
// grid (B*T2, 2): each block 128 nodes
#define K3B_SMEM ((128*65) * 4)
__global__ __launch_bounds__(256) void k3b_ln(float* __restrict__ out) {
    extern __shared__ float sm[];
    float* smy = sm;                    // [128][65]
    int bt = blockIdx.x;
    int b = bt / T2, t = bt % T2;
    int nbase = blockIdx.y * 128;
    int tid = threadIdx.x;

    float S = 0.f, Q = 0.f;
#pragma unroll
    for (int k = 0; k < 4; k++) {
        S += g_part[(bt * 4 + k) * 2 + 0];
        Q += g_part[(bt * 4 + k) * 2 + 1];
    }
    const float invM = 1.f / 16384.f;
    float mu = S * invM;
    float var = Q * invM - mu * mu;
    float rstd = rsqrtf(var + 1e-5f);

    for (int idx = tid; idx < 128 * C2; idx += 256) {
        int nl = idx >> 6, c = idx & 63;
        smy[nl * 65 + c] = g_ys[(bt * NN + nbase + nl) * C2 + c];
    }
    __syncthreads();

    int nl = tid & 127, n = nbase + nl;
    int coff = (tid >> 7) * 32;
    for (int cc = 0; cc < 32; cc++) {
        int c = coff + cc;
        float v = (smy[nl * 65 + c] - mu) * rstd;
        v = fmaf(v, g_lnw[c * NN + n], g_lnb[c * NN + n]);
        out[((b * C2 + c) * T2 + t) * NN + n] = v;
    }
}

// ---------------- launch ---------------------------------------------------
extern "C" void kernel_launch(void* const* d_in, const int* in_sizes, int n_in,
                              void* d_out, int out_size) {
    const float* x       = (const float*)d_in[0];
    const float* adj     = (const float*)d_in[1];
    const float* conv1_w = (const float*)d_in[2];
    const float* conv1_b = (const float*)d_in[3];
    const float* conv2_w = (const float*)d_in[4];
    const float* conv2_b = (const float*)d_in[5];
    const float* W_heads = (const float*)d_in[6];
    const float* a_heads = (const float*)d_in[7];
    const float* ln_w    = (const float*)d_in[8];
    const float* ln_b    = (const float*)d_in[9];
    float* out = (float*)d_out;

    cudaFuncSetAttribute(k1_conv1,  cudaFuncAttributeMaxDynamicSharedMemorySize, K1_SMEM);
    cudaFuncSetAttribute(k2_gat,    cudaFuncAttributeMaxDynamicSharedMemorySize, K2_SMEM);
    cudaFuncSetAttribute(k3a_conv2, cudaFuncAttributeMaxDynamicSharedMemorySize, K3A_SMEM);
    cudaFuncSetAttribute(k3b_ln,    cudaFuncAttributeMaxDynamicSharedMemorySize, K3B_SMEM);

    k0_prep<<<16, 256>>>(adj, W_heads, a_heads, ln_w, ln_b);
    k1_conv1<<<dim3(BB * T1, 2), 256, K1_SMEM>>>(x, conv1_w, conv1_b);
    k2_gat<<<dim3(BB * T1, 4), 256, K2_SMEM>>>();
    k3a_conv2<<<dim3(BB * T2, 4), 256, K3A_SMEM>>>(conv2_w, conv2_b);
    k3b_ln<<<dim3(BB * T2, 2), 256, K3B_SMEM>>>(out);
}